// round 8
// baseline (speedup 1.0000x reference)
#include <cuda_runtime.h>
#include <cuda_bf16.h>
#include <cstdint>

#define NUM_USERS 100000
#define N_NODES   300000
#define NNZ_E     1200000
#define DIM       64
#define OUT_COLS  256
#define TILE_M    128
#define N_TILES   ((N_NODES + TILE_M - 1) / TILE_M)   // 2344

// ---- dense-kernel smem byte offsets; ST = 144-byte row stride (72 bf16) ----
#define ST        144
#define SM_BIAS   0                      // 64 floats
#define SM_S_HI   256
#define SM_S_LO   (SM_S_HI + 128*ST)     // 18688
#define SM_P_HI   (SM_S_LO + 128*ST)
#define SM_P_LO   (SM_P_HI + 128*ST)
#define SM_WC_HI  (SM_P_LO + 128*ST)     // W^T tiles: 64 rows x 144B
#define SM_WC_LO  (SM_WC_HI + 64*ST)
#define SM_WE_HI  (SM_WC_LO + 64*ST)
#define SM_WE_LO  (SM_WE_HI + 64*ST)
#define SMEM_TOTAL (SM_WE_LO + 64*ST)    // 110848 bytes

__device__ __align__(16) float g_emb[(size_t)N_NODES * DIM];
__device__ __align__(16) float g_side[(size_t)N_NODES * DIM];

// ---------------------------------------------------------------------------
__device__ __forceinline__ void mma16816(float* c, const uint32_t* a, const uint32_t* b) {
    asm volatile(
        "mma.sync.aligned.m16n8k16.row.col.f32.bf16.bf16.f32 "
        "{%0,%1,%2,%3}, {%4,%5,%6,%7}, {%8,%9}, {%0,%1,%2,%3};"
        : "+f"(c[0]), "+f"(c[1]), "+f"(c[2]), "+f"(c[3])
        : "r"(a[0]), "r"(a[1]), "r"(a[2]), "r"(a[3]), "r"(b[0]), "r"(b[1]));
}

// split a float pair into bf16 hi + lo packed pairs
__device__ __forceinline__ void split2(float a, float b, __nv_bfloat162& h2, __nv_bfloat162& l2) {
    h2 = __floats2bfloat162_rn(a, b);
    float ha = __low2float(h2), hb = __high2float(h2);
    l2 = __floats2bfloat162_rn(a - ha, b - hb);
}

// ---------------------------------------------------------------------------
// concat + zero g_side + write layer-0 output slice
// ---------------------------------------------------------------------------
__global__ void concat_kernel(const float* __restrict__ ue,
                              const float* __restrict__ ie,
                              float* __restrict__ out) {
    int idx = blockIdx.x * blockDim.x + threadIdx.x;
    const int total = N_NODES * (DIM / 4);
    if (idx >= total) return;
    int node = idx >> 4;
    int c4   = idx & 15;
    float4 v;
    if (node < NUM_USERS) v = ((const float4*)ue)[node * 16 + c4];
    else                  v = ((const float4*)ie)[(node - NUM_USERS) * 16 + c4];
    ((float4*)g_emb)[idx] = v;
    ((float4*)g_side)[idx] = make_float4(0.f, 0.f, 0.f, 0.f);
    ((float4*)out)[(size_t)node * (OUT_COLS / 4) + c4] = v;
}

// ---------------------------------------------------------------------------
// SpMM scatter: side[rows[e]] += vals[e] * emb[cols[e]]  (16 lanes/edge, v4 red)
// ---------------------------------------------------------------------------
__global__ void spmm_kernel(const int* __restrict__ rows,
                            const int* __restrict__ cols,
                            const float* __restrict__ vals) {
    int idx = blockIdx.x * blockDim.x + threadIdx.x;
    if (idx >= NNZ_E * 16) return;
    int e = idx >> 4;
    int c = idx & 15;
    int r  = __ldg(&rows[e]);
    int cl = __ldg(&cols[e]);
    float v = __ldg(&vals[e]);
    float4 x = ((const float4*)g_emb)[(size_t)cl * 16 + c];
    float* dst = g_side + (size_t)r * DIM + c * 4;
    asm volatile("red.global.add.v4.f32 [%0], {%1, %2, %3, %4};"
                 :: "l"(dst), "f"(v * x.x), "f"(v * x.y), "f"(v * x.z), "f"(v * x.w)
                 : "memory");
}

// ---------------------------------------------------------------------------
// Dense via mma.sync (HMMA 16816 bf16): D = S·Wc^T + P·We^T, hi/lo split,
// 6 chained products into one fp32 accumulator. 8 warps x 16-row strips.
// Epilogue: bias + leaky + quad-shuffle L2-norm. Re-zeroes g_side tile.
// ---------------------------------------------------------------------------
extern __shared__ char dsmem[];

__global__ void __launch_bounds__(256, 2) dense_mma_kernel(
    const float* __restrict__ Wc, const float* __restrict__ bc,
    const float* __restrict__ We, const float* __restrict__ be,
    float* __restrict__ out_col)
{
    const int tid = threadIdx.x;
    const int wid = tid >> 5;
    const int lid = tid & 31;
    const int g   = lid >> 2;        // group id (row within fragment)
    const int tig = lid & 3;         // thread-in-group (col pair)
    const int nb  = blockIdx.x * TILE_M;
    float* sBias = (float*)(dsmem + SM_BIAS);

    // ---- weights: W^T[n][k] split into hi/lo bf16 ----
    for (int t = tid; t < 4096; t += 256) {
        int k = t >> 6, j = t & 63;
        float wc = __ldg(&Wc[t]);
        float we = __ldg(&We[t]);
        uint32_t off = (uint32_t)(j * ST + k * 2);
        __nv_bfloat16 h, l;
        h = __float2bfloat16(wc); l = __float2bfloat16(wc - __bfloat162float(h));
        *(__nv_bfloat16*)(dsmem + SM_WC_HI + off) = h;
        *(__nv_bfloat16*)(dsmem + SM_WC_LO + off) = l;
        h = __float2bfloat16(we); l = __float2bfloat16(we - __bfloat162float(h));
        *(__nv_bfloat16*)(dsmem + SM_WE_HI + off) = h;
        *(__nv_bfloat16*)(dsmem + SM_WE_LO + off) = l;
    }
    for (int j = tid; j < 64; j += 256) sBias[j] = __ldg(&bc[j]) + __ldg(&be[j]);

    // ---- A tiles: S and P = S*E, hi/lo split; re-zero g_side ----
    for (int i = tid; i < TILE_M * 16; i += 256) {
        int r  = i >> 4;
        int c4 = i & 15;
        int node = nb + r;
        float4 s = make_float4(0.f, 0.f, 0.f, 0.f);
        float4 e = make_float4(0.f, 0.f, 0.f, 0.f);
        if (node < N_NODES) {
            s = ((const float4*)g_side)[(size_t)node * 16 + c4];
            e = ((const float4*)g_emb)[(size_t)node * 16 + c4];
            ((float4*)g_side)[(size_t)node * 16 + c4] = make_float4(0.f, 0.f, 0.f, 0.f);
        }
        float4 p = make_float4(s.x * e.x, s.y * e.y, s.z * e.z, s.w * e.w);
        uint32_t o0 = (uint32_t)(r * ST + c4 * 8);       // bytes, pair (k,k+1)
        __nv_bfloat162 h2, l2;
        split2(s.x, s.y, h2, l2);
        *(__nv_bfloat162*)(dsmem + SM_S_HI + o0)     = h2;
        *(__nv_bfloat162*)(dsmem + SM_S_LO + o0)     = l2;
        split2(s.z, s.w, h2, l2);
        *(__nv_bfloat162*)(dsmem + SM_S_HI + o0 + 4) = h2;
        *(__nv_bfloat162*)(dsmem + SM_S_LO + o0 + 4) = l2;
        split2(p.x, p.y, h2, l2);
        *(__nv_bfloat162*)(dsmem + SM_P_HI + o0)     = h2;
        *(__nv_bfloat162*)(dsmem + SM_P_LO + o0)     = l2;
        split2(p.z, p.w, h2, l2);
        *(__nv_bfloat162*)(dsmem + SM_P_HI + o0 + 4) = h2;
        *(__nv_bfloat162*)(dsmem + SM_P_LO + o0 + 4) = l2;
    }
    __syncthreads();

    // ---- MMA mainloop: k outer, n inner ----
    float acc[8][4];
    #pragma unroll
    for (int n = 0; n < 8; n++)
        #pragma unroll
        for (int q = 0; q < 4; q++) acc[n][q] = 0.f;

    const int arow = wid * 16 + g;
    #pragma unroll
    for (int kk = 0; kk < 4; kk++) {
        uint32_t ao = (uint32_t)(arow * ST + kk * 32 + tig * 4);
        uint32_t s_hi[4], s_lo[4], p_hi[4], p_lo[4];
        s_hi[0] = *(uint32_t*)(dsmem + SM_S_HI + ao);
        s_hi[1] = *(uint32_t*)(dsmem + SM_S_HI + ao + 8 * ST);
        s_hi[2] = *(uint32_t*)(dsmem + SM_S_HI + ao + 16);
        s_hi[3] = *(uint32_t*)(dsmem + SM_S_HI + ao + 8 * ST + 16);
        s_lo[0] = *(uint32_t*)(dsmem + SM_S_LO + ao);
        s_lo[1] = *(uint32_t*)(dsmem + SM_S_LO + ao + 8 * ST);
        s_lo[2] = *(uint32_t*)(dsmem + SM_S_LO + ao + 16);
        s_lo[3] = *(uint32_t*)(dsmem + SM_S_LO + ao + 8 * ST + 16);
        p_hi[0] = *(uint32_t*)(dsmem + SM_P_HI + ao);
        p_hi[1] = *(uint32_t*)(dsmem + SM_P_HI + ao + 8 * ST);
        p_hi[2] = *(uint32_t*)(dsmem + SM_P_HI + ao + 16);
        p_hi[3] = *(uint32_t*)(dsmem + SM_P_HI + ao + 8 * ST + 16);
        p_lo[0] = *(uint32_t*)(dsmem + SM_P_LO + ao);
        p_lo[1] = *(uint32_t*)(dsmem + SM_P_LO + ao + 8 * ST);
        p_lo[2] = *(uint32_t*)(dsmem + SM_P_LO + ao + 16);
        p_lo[3] = *(uint32_t*)(dsmem + SM_P_LO + ao + 8 * ST + 16);

        #pragma unroll
        for (int n = 0; n < 8; n++) {
            uint32_t bo = (uint32_t)((n * 8 + g) * ST + kk * 32 + tig * 4);
            uint32_t bch[2], bcl[2], beh[2], bel[2];
            bch[0] = *(uint32_t*)(dsmem + SM_WC_HI + bo);
            bch[1] = *(uint32_t*)(dsmem + SM_WC_HI + bo + 16);
            bcl[0] = *(uint32_t*)(dsmem + SM_WC_LO + bo);
            bcl[1] = *(uint32_t*)(dsmem + SM_WC_LO + bo + 16);
            beh[0] = *(uint32_t*)(dsmem + SM_WE_HI + bo);
            beh[1] = *(uint32_t*)(dsmem + SM_WE_HI + bo + 16);
            bel[0] = *(uint32_t*)(dsmem + SM_WE_LO + bo);
            bel[1] = *(uint32_t*)(dsmem + SM_WE_LO + bo + 16);
            mma16816(acc[n], s_hi, bch);
            mma16816(acc[n], s_lo, bch);
            mma16816(acc[n], s_hi, bcl);
            mma16816(acc[n], p_hi, beh);
            mma16816(acc[n], p_lo, beh);
            mma16816(acc[n], p_hi, bel);
        }
    }

    // ---- epilogue: rows arow and arow+8 ----
    float v0[16], v1[16];
    float q0 = 0.f, q1 = 0.f;
    #pragma unroll
    for (int n = 0; n < 8; n++) {
        int col = n * 8 + tig * 2;
        float b0 = sBias[col], b1 = sBias[col + 1];
        float x;
        x = acc[n][0] + b0; x = x >= 0.f ? x : 0.2f * x; v0[2*n]   = x; q0 += x * x;
        x = acc[n][1] + b1; x = x >= 0.f ? x : 0.2f * x; v0[2*n+1] = x; q0 += x * x;
        x = acc[n][2] + b0; x = x >= 0.f ? x : 0.2f * x; v1[2*n]   = x; q1 += x * x;
        x = acc[n][3] + b1; x = x >= 0.f ? x : 0.2f * x; v1[2*n+1] = x; q1 += x * x;
    }
    // reduce across the 4 lanes (tig 0..3) sharing each row
    q0 += __shfl_xor_sync(0xffffffffu, q0, 1);
    q0 += __shfl_xor_sync(0xffffffffu, q0, 2);
    q1 += __shfl_xor_sync(0xffffffffu, q1, 1);
    q1 += __shfl_xor_sync(0xffffffffu, q1, 2);
    float sc0 = 1.0f / fmaxf(sqrtf(q0), 1e-12f);
    float sc1 = 1.0f / fmaxf(sqrtf(q1), 1e-12f);

    int node0 = nb + arow;
    int node1 = node0 + 8;
    if (node0 < N_NODES) {
        #pragma unroll
        for (int n = 0; n < 8; n++) {
            int col = n * 8 + tig * 2;
            *(float2*)&g_emb[(size_t)node0 * DIM + col] = make_float2(v0[2*n], v0[2*n+1]);
            *(float2*)&out_col[(size_t)node0 * OUT_COLS + col] =
                make_float2(v0[2*n] * sc0, v0[2*n+1] * sc0);
        }
    }
    if (node1 < N_NODES) {
        #pragma unroll
        for (int n = 0; n < 8; n++) {
            int col = n * 8 + tig * 2;
            *(float2*)&g_emb[(size_t)node1 * DIM + col] = make_float2(v1[2*n], v1[2*n+1]);
            *(float2*)&out_col[(size_t)node1 * OUT_COLS + col] =
                make_float2(v1[2*n] * sc1, v1[2*n+1] * sc1);
        }
    }
}

// ---------------------------------------------------------------------------
extern "C" void kernel_launch(void* const* d_in, const int* in_sizes, int n_in,
                              void* d_out, int out_size) {
    const int*   rows = (const int*)  d_in[0];
    const int*   cols = (const int*)  d_in[1];
    const float* vals = (const float*)d_in[2];
    const float* ue   = (const float*)d_in[3];
    const float* ie   = (const float*)d_in[4];
    const float* Wc   = (const float*)d_in[5];
    const float* bc   = (const float*)d_in[6];
    const float* We   = (const float*)d_in[7];
    const float* be   = (const float*)d_in[8];
    float* out = (float*)d_out;

    cudaFuncSetAttribute(dense_mma_kernel,
                         cudaFuncAttributeMaxDynamicSharedMemorySize, SMEM_TOTAL);

    const int vec_elems = N_NODES * (DIM / 4);
    concat_kernel<<<(vec_elems + 255) / 256, 256>>>(ue, ie, out);

    for (int l = 0; l < 3; l++) {
        spmm_kernel<<<(NNZ_E * 16 + 255) / 256, 256>>>(rows, cols, vals);
        dense_mma_kernel<<<N_TILES, 256, SMEM_TOTAL>>>(
            Wc + l * DIM * DIM, bc + l * DIM,
            We + l * DIM * DIM, be + l * DIM,
            out + (size_t)(l + 1) * DIM);
    }
}